// round 8
// baseline (speedup 1.0000x reference)
#include <cuda_runtime.h>

#define NN   50000
#define NSEG 150000          // 3 relations x NN segments, v = r*NN + node
#define NT   256
#define EMAX 4500000
#define SCAN_BS 1024

// ---------------- scratch (static device globals; no allocs) ----------------
__device__ int    g_is64;
__device__ int    g_dout[NSEG];          // out-degree per (r,node)
__device__ int    g_din [NSEG];          // in-degree per (r,node)
__device__ int2   g_edges[EMAX];         // compact (src seg, dst seg)
__device__ int    g_off [NSEG + 1];      // value-CSR offsets by dst segment
__device__ int    g_cur [NSEG];          // fill cursors
__device__ int    g_part[256];           // scan block partials
__device__ float  g_h1  [NSEG * 16];     // aout-scaled layer-1 features (9.6MB)
__device__ float4 g_tv  [EMAX * 4];      // dst-sorted 64B value rows (288MB)
__device__ float  g_m   [NSEG * 16];     // per-segment raw sums
__device__ float  g_s   [NSEG];          // scalar layer-2 messages
__device__ float  g_o2  [NSEG];          // scalar layer-2 accumulators

// ---------------- dtype detection ----------------
__global__ void k_detect(const unsigned* __restrict__ p, int n) {
    __shared__ int found;
    if (threadIdx.x == 0) found = 0;
    __syncthreads();
    int f = 0;
    for (int i = threadIdx.x; i < n; i += blockDim.x)
        if (p[2 * i + 1] != 0u) f = 1;
    if (f) atomicOr(&found, 1);
    __syncthreads();
    if (threadIdx.x == 0) g_is64 = found ? 0 : 1;
}

__device__ __forceinline__ int ldidx(const void* __restrict__ p, int i) {
    return g_is64 ? (int)__ldg((const long long*)p + i)
                  : __ldg((const int*)p + i);
}

__device__ __forceinline__ float rs_of(int cnt) {
    return rsqrtf((float)(cnt > 0 ? cnt : 1));
}

// ---------------- zero degree counters ----------------
__global__ void k_zero() {
    int i = blockIdx.x * blockDim.x + threadIdx.x;
    if (i < NSEG) { g_dout[i] = 0; g_din[i] = 0; }
}

// ------- degrees + compact int2 edge emit (single pass over raw idx) --------
__global__ void k_degc(const void* __restrict__ src, const void* __restrict__ dst,
                       int E, int r, int eoff) {
    int e = blockIdx.x * blockDim.x + threadIdx.x;
    if (e >= E) return;
    int s = r * NN + ldidx(src, e);
    int d = r * NN + ldidx(dst, e);
    atomicAdd(&g_dout[s], 1);
    atomicAdd(&g_din [d], 1);
    g_edges[eoff + e] = make_int2(s, d);
}

// ---------------- exclusive scan over g_din ----------------
__global__ void k_scan1() {
    __shared__ int ws[32];
    int b = blockIdx.x, t = threadIdx.x;
    int v = b * SCAN_BS + t;
    int val = (v < NSEG) ? g_din[v] : 0;
    #pragma unroll
    for (int o = 16; o; o >>= 1) val += __shfl_down_sync(0xffffffffu, val, o);
    if ((t & 31) == 0) ws[t >> 5] = val;
    __syncthreads();
    if (t < 32) {
        int x = ws[t];
        #pragma unroll
        for (int o = 16; o; o >>= 1) x += __shfl_down_sync(0xffffffffu, x, o);
        if (t == 0) g_part[b] = x;
    }
}

__global__ void k_scan2(int nblk) {
    __shared__ int sh[256];
    int t = threadIdx.x;
    sh[t] = (t < nblk) ? g_part[t] : 0;
    __syncthreads();
    for (int o = 1; o < 256; o <<= 1) {
        int y = (t >= o) ? sh[t - o] : 0;
        __syncthreads();
        sh[t] += y;
        __syncthreads();
    }
    if (t < nblk) g_part[t] = (t == 0) ? 0 : sh[t - 1];
    if (t == 0) g_off[NSEG] = sh[nblk - 1];
}

__global__ void k_scan3() {
    __shared__ int ws[32];
    int b = blockIdx.x, t = threadIdx.x;
    int v = b * SCAN_BS + t;
    int lane = t & 31, wid = t >> 5;
    int val = (v < NSEG) ? g_din[v] : 0;
    int x = val;
    #pragma unroll
    for (int o = 1; o < 32; o <<= 1) {
        int y = __shfl_up_sync(0xffffffffu, x, o);
        if (lane >= o) x += y;
    }
    if (lane == 31) ws[wid] = x;
    __syncthreads();
    if (wid == 0) {
        int w = ws[lane];
        #pragma unroll
        for (int o = 1; o < 32; o <<= 1) {
            int y = __shfl_up_sync(0xffffffffu, w, o);
            if (lane >= o) w += y;
        }
        ws[lane] = w;
    }
    __syncthreads();
    int base = g_part[b] + (wid > 0 ? ws[wid - 1] : 0);
    int excl = base + x - val;
    if (v < NSEG) { g_off[v] = excl; g_cur[v] = excl; }
}

// ---------------- layer 1: per-node transform ----------------
__global__ void k_layer1_node(const float* __restrict__ x, const float* __restrict__ W1) {
    __shared__ float sW[3 * 32 * 16];
    for (int i = threadIdx.x; i < 1536; i += blockDim.x) sW[i] = W1[i];
    __syncthreads();
    int n = blockIdx.x * blockDim.x + threadIdx.x;
    if (n >= NN) return;
    float xv[32];
    #pragma unroll
    for (int j = 0; j < 8; j++) {
        float4 v = __ldg((const float4*)(x + (size_t)n * 32) + j);
        xv[4*j] = v.x; xv[4*j+1] = v.y; xv[4*j+2] = v.z; xv[4*j+3] = v.w;
    }
    #pragma unroll
    for (int r = 0; r < 3; r++) {
        float a = rs_of(g_dout[r * NN + n]);
        float y[16];
        #pragma unroll
        for (int f = 0; f < 16; f++) y[f] = 0.f;
        #pragma unroll
        for (int j = 0; j < 32; j++) {
            float xj = xv[j];
            #pragma unroll
            for (int f = 0; f < 16; f++)
                y[f] += xj * sW[r * 512 + j * 16 + f];
        }
        float* hp = &g_h1[(size_t)(r * NN + n) * 16];
        #pragma unroll
        for (int f = 0; f < 16; f += 4)
            *(float4*)(hp + f) = make_float4(a*y[f], a*y[f+1], a*y[f+2], a*y[f+3]);
    }
}

// ------ materialize dst-sorted value rows: 1 thread/edge, 64B full-sector ---
__global__ void k_fillval(int Etot) {
    int e = blockIdx.x * blockDim.x + threadIdx.x;
    if (e >= Etot) return;
    int2 ed = __ldg((const int2*)&g_edges[e]);
    const float4* hp = (const float4*)&g_h1[(size_t)ed.x * 16];
    float4 v0 = __ldg(hp + 0);
    float4 v1 = __ldg(hp + 1);
    float4 v2 = __ldg(hp + 2);
    float4 v3 = __ldg(hp + 3);
    int pos = atomicAdd(&g_cur[ed.y], 1);
    float4* tp = &g_tv[(size_t)pos * 4];
    tp[0] = v0; tp[1] = v1; tp[2] = v2; tp[3] = v3;
}

// ------ segmented sum over CONSECUTIVE rows: warp/segment, streaming --------
__global__ void k_segsum() {
    int gw = (blockIdx.x * blockDim.x + threadIdx.x) >> 5;
    int lane = threadIdx.x & 31;
    if (gw >= NSEG) return;
    int base = __ldg(&g_off[gw]);
    int end  = __ldg(&g_off[gw + 1]);
    int sub = lane >> 2, c = lane & 3;        // 8 row-teams x 4 chunks
    float4 acc = make_float4(0.f, 0.f, 0.f, 0.f);
    int row = base + sub;
    // unroll x2: two independent 512B-contiguous warp loads in flight
    for (; row + 8 < end; row += 16) {
        float4 v0 = __ldg(&g_tv[(size_t)row * 4 + c]);
        float4 v1 = __ldg(&g_tv[(size_t)(row + 8) * 4 + c]);
        acc.x += v0.x + v1.x; acc.y += v0.y + v1.y;
        acc.z += v0.z + v1.z; acc.w += v0.w + v1.w;
    }
    for (; row < end; row += 8) {
        float4 v = __ldg(&g_tv[(size_t)row * 4 + c]);
        acc.x += v.x; acc.y += v.y; acc.z += v.z; acc.w += v.w;
    }
    #pragma unroll
    for (int o = 4; o <= 16; o <<= 1) {
        acc.x += __shfl_xor_sync(0xffffffffu, acc.x, o);
        acc.y += __shfl_xor_sync(0xffffffffu, acc.y, o);
        acc.z += __shfl_xor_sync(0xffffffffu, acc.z, o);
        acc.w += __shfl_xor_sync(0xffffffffu, acc.w, o);
    }
    if (lane < 4)
        *(float4*)&g_m[(size_t)gw * 16 + lane * 4] = acc;   // raw sum; ain in combine
}

// ---------------- combine + relu + layer-2 node transform ----------------
__global__ void k_combine(const float* __restrict__ b1, const float* __restrict__ W2) {
    __shared__ float sW2[48], sb1[48];
    if (threadIdx.x < 48) {
        sW2[threadIdx.x] = W2[threadIdx.x];
        sb1[threadIdx.x] = b1[threadIdx.x];
    }
    __syncthreads();
    int n = blockIdx.x * blockDim.x + threadIdx.x;
    if (n >= NN) return;
    float acc[16];
    #pragma unroll
    for (int f = 0; f < 16; f++) acc[f] = 0.f;
    #pragma unroll
    for (int r = 0; r < 3; r++) {
        float ain = rs_of(g_din[r * NN + n]);
        const float* mp = &g_m[(size_t)(r * NN + n) * 16];
        #pragma unroll
        for (int f = 0; f < 16; f += 4) {
            float4 v = *(const float4*)(mp + f);
            acc[f]   += v.x * ain + sb1[r*16 + f];
            acc[f+1] += v.y * ain + sb1[r*16 + f + 1];
            acc[f+2] += v.z * ain + sb1[r*16 + f + 2];
            acc[f+3] += v.w * ain + sb1[r*16 + f + 3];
        }
    }
    #pragma unroll
    for (int f = 0; f < 16; f++) acc[f] = fmaxf(acc[f], 0.f);
    #pragma unroll
    for (int r = 0; r < 3; r++) {
        float aout = rs_of(g_dout[r * NN + n]);
        float dot = 0.f;
        #pragma unroll
        for (int f = 0; f < 16; f++) dot += acc[f] * sW2[r*16 + f];
        g_s [r * NN + n] = aout * dot;
        g_o2[r * NN + n] = 0.f;
    }
}

// ---------------- layer 2: scalar edge scatter (small, at REDG wall) --------
__global__ void k_scatter1(int Etot) {
    int e = blockIdx.x * blockDim.x + threadIdx.x;
    if (e >= Etot) return;
    int2 ed = __ldg((const int2*)&g_edges[e]);
    float v = __ldg(&g_s[ed.x]);
    atomicAdd(&g_o2[ed.y], v);
}

// ---------------- final ----------------
__global__ void k_final(float* __restrict__ out, const float* __restrict__ b2) {
    int n = blockIdx.x * blockDim.x + threadIdx.x;
    if (n >= NN) return;
    float o = __ldg(b2) + __ldg(b2 + 1) + __ldg(b2 + 2);
    #pragma unroll
    for (int r = 0; r < 3; r++)
        o += g_o2[r * NN + n] * rs_of(g_din[r * NN + n]);
    out[n] = o;
}

// ---------------- host ----------------
extern "C" void kernel_launch(void* const* d_in, const int* in_sizes, int n_in,
                              void* d_out, int out_size) {
    const float* x  = (const float*)d_in[0];
    const void*  src[3] = { d_in[1], d_in[3], d_in[5] };
    const void*  dst[3] = { d_in[2], d_in[4], d_in[6] };
    int          E[3]   = { in_sizes[1], in_sizes[3], in_sizes[5] };
    const float* W1 = (const float*)d_in[7];
    const float* b1 = (const float*)d_in[8];
    const float* W2 = (const float*)d_in[9];
    const float* b2 = (const float*)d_in[10];
    float*       out = (float*)d_out;

    int Etot = E[0] + E[1] + E[2];
    if (Etot > EMAX) Etot = EMAX;

    int nprobe = E[0] < 2048 ? E[0] : 2048;
    k_detect<<<1, NT>>>((const unsigned*)d_in[1], nprobe);

    k_zero<<<(NSEG + NT - 1) / NT, NT>>>();
    int eoff = 0;
    for (int r = 0; r < 3; r++) {
        k_degc<<<(E[r] + NT - 1) / NT, NT>>>(src[r], dst[r], E[r], r, eoff);
        eoff += E[r];
    }

    int nblk = (NSEG + SCAN_BS - 1) / SCAN_BS;   // 147
    k_scan1<<<nblk, SCAN_BS>>>();
    k_scan2<<<1, 256>>>(nblk);
    k_scan3<<<nblk, SCAN_BS>>>();

    k_layer1_node<<<(NN + NT - 1) / NT, NT>>>(x, W1);
    k_fillval<<<(Etot + NT - 1) / NT, NT>>>(Etot);

    long long thr = (long long)NSEG * 32;
    k_segsum<<<(int)((thr + NT - 1) / NT), NT>>>();

    k_combine<<<(NN + NT - 1) / NT, NT>>>(b1, W2);
    k_scatter1<<<(Etot + NT - 1) / NT, NT>>>(Etot);

    k_final<<<(NN + NT - 1) / NT, NT>>>(out, b2);
}

// round 9
// speedup vs baseline: 1.3824x; 1.3824x over previous
#include <cuda_runtime.h>

#define NN    50000
#define NSEG  150000         // 3 relations x NN segments, v = r*NN + node
#define NT    256
#define EMAX  4500000
#define CHUNK 16
#define SCAN_BS 1024

// ---------------- scratch (static device globals; no allocs) ----------------
__device__ int    g_is64;
__device__ int    g_dout[NSEG];          // out-degree per (r,node)
__device__ int    g_din [NSEG];          // in-degree per (r,node)
__device__ int2   g_edges[EMAX];         // compact (src seg, dst seg), unsorted
__device__ int    g_off [NSEG + 1];      // sorted-edge offsets by dst segment
__device__ int    g_cur [NSEG];          // fill cursors
__device__ int    g_part[256];           // scan block partials
__device__ int4   g_sortv[EMAX / 2 + 1]; // dst-sorted edges, 2 per int4 (s0,d0,s1,d1)
__device__ float  g_h1  [NSEG * 16];     // aout-scaled layer-1 features (9.6MB)
__device__ float  g_m   [NSEG * 16];     // aggregation buffers (zeroed in layer1)
__device__ float  g_s   [NSEG];          // scalar layer-2 messages
__device__ float  g_o2  [NSEG];          // scalar layer-2 accumulators

// ---------------- dtype detection ----------------
__global__ void k_detect(const unsigned* __restrict__ p, int n) {
    __shared__ int found;
    if (threadIdx.x == 0) found = 0;
    __syncthreads();
    int f = 0;
    for (int i = threadIdx.x; i < n; i += blockDim.x)
        if (p[2 * i + 1] != 0u) f = 1;
    if (f) atomicOr(&found, 1);
    __syncthreads();
    if (threadIdx.x == 0) g_is64 = found ? 0 : 1;
}

__device__ __forceinline__ int ldidx(const void* __restrict__ p, int i) {
    return g_is64 ? (int)__ldg((const long long*)p + i)
                  : __ldg((const int*)p + i);
}

__device__ __forceinline__ float rs_of(int cnt) {
    return rsqrtf((float)(cnt > 0 ? cnt : 1));
}

// ---------------- zero degree counters ----------------
__global__ void k_zero() {
    int i = blockIdx.x * blockDim.x + threadIdx.x;
    if (i < NSEG) { g_dout[i] = 0; g_din[i] = 0; }
}

// ------- degrees + compact int2 edge emit (single pass over raw idx) --------
__global__ void k_degc(const void* __restrict__ src, const void* __restrict__ dst,
                       int E, int r, int eoff) {
    int e = blockIdx.x * blockDim.x + threadIdx.x;
    if (e >= E) return;
    int s = r * NN + ldidx(src, e);
    int d = r * NN + ldidx(dst, e);
    atomicAdd(&g_dout[s], 1);
    atomicAdd(&g_din [d], 1);
    g_edges[eoff + e] = make_int2(s, d);
}

// ---------------- exclusive scan over g_din ----------------
__global__ void k_scan1() {
    __shared__ int ws[32];
    int b = blockIdx.x, t = threadIdx.x;
    int v = b * SCAN_BS + t;
    int val = (v < NSEG) ? g_din[v] : 0;
    #pragma unroll
    for (int o = 16; o; o >>= 1) val += __shfl_down_sync(0xffffffffu, val, o);
    if ((t & 31) == 0) ws[t >> 5] = val;
    __syncthreads();
    if (t < 32) {
        int x = ws[t];
        #pragma unroll
        for (int o = 16; o; o >>= 1) x += __shfl_down_sync(0xffffffffu, x, o);
        if (t == 0) g_part[b] = x;
    }
}

__global__ void k_scan2(int nblk) {
    __shared__ int sh[256];
    int t = threadIdx.x;
    sh[t] = (t < nblk) ? g_part[t] : 0;
    __syncthreads();
    for (int o = 1; o < 256; o <<= 1) {
        int y = (t >= o) ? sh[t - o] : 0;
        __syncthreads();
        sh[t] += y;
        __syncthreads();
    }
    if (t < nblk) g_part[t] = (t == 0) ? 0 : sh[t - 1];
    if (t == 0) g_off[NSEG] = sh[nblk - 1];
}

__global__ void k_scan3() {
    __shared__ int ws[32];
    int b = blockIdx.x, t = threadIdx.x;
    int v = b * SCAN_BS + t;
    int lane = t & 31, wid = t >> 5;
    int val = (v < NSEG) ? g_din[v] : 0;
    int x = val;
    #pragma unroll
    for (int o = 1; o < 32; o <<= 1) {
        int y = __shfl_up_sync(0xffffffffu, x, o);
        if (lane >= o) x += y;
    }
    if (lane == 31) ws[wid] = x;
    __syncthreads();
    if (wid == 0) {
        int w = ws[lane];
        #pragma unroll
        for (int o = 1; o < 32; o <<= 1) {
            int y = __shfl_up_sync(0xffffffffu, w, o);
            if (lane >= o) w += y;
        }
        ws[lane] = w;
    }
    __syncthreads();
    int base = g_part[b] + (wid > 0 ? ws[wid - 1] : 0);
    int excl = base + x - val;
    if (v < NSEG) { g_off[v] = excl; g_cur[v] = excl; }
}

// ---------------- sort edges by dst via cursor scatter ----------------
__global__ void k_fill(int Etot) {
    int e = blockIdx.x * blockDim.x + threadIdx.x;
    if (e >= Etot) return;
    int2 ed = __ldg((const int2*)&g_edges[e]);
    int pos = atomicAdd(&g_cur[ed.y], 1);
    ((int2*)g_sortv)[pos] = ed;
}

// ---------------- layer 1: per-node transform (and zero g_m) ----------------
__global__ void k_layer1_node(const float* __restrict__ x, const float* __restrict__ W1) {
    __shared__ float sW[3 * 32 * 16];
    for (int i = threadIdx.x; i < 1536; i += blockDim.x) sW[i] = W1[i];
    __syncthreads();
    int n = blockIdx.x * blockDim.x + threadIdx.x;
    if (n >= NN) return;
    float xv[32];
    #pragma unroll
    for (int j = 0; j < 8; j++) {
        float4 v = __ldg((const float4*)(x + (size_t)n * 32) + j);
        xv[4*j] = v.x; xv[4*j+1] = v.y; xv[4*j+2] = v.z; xv[4*j+3] = v.w;
    }
    #pragma unroll
    for (int r = 0; r < 3; r++) {
        float a = rs_of(g_dout[r * NN + n]);
        float y[16];
        #pragma unroll
        for (int f = 0; f < 16; f++) y[f] = 0.f;
        #pragma unroll
        for (int j = 0; j < 32; j++) {
            float xj = xv[j];
            #pragma unroll
            for (int f = 0; f < 16; f++)
                y[f] += xj * sW[r * 512 + j * 16 + f];
        }
        float* hp = &g_h1[(size_t)(r * NN + n) * 16];
        float* mp = &g_m [(size_t)(r * NN + n) * 16];
        #pragma unroll
        for (int f = 0; f < 16; f += 4) {
            *(float4*)(hp + f) = make_float4(a*y[f], a*y[f+1], a*y[f+2], a*y[f+3]);
            *(float4*)(mp + f) = make_float4(0.f, 0.f, 0.f, 0.f);
        }
    }
}

// ---- layer 1 aggregate: thread walks CHUNK sorted edges, merges runs in ----
// ---- registers, one RED.128x4 per run-piece (lane count / ~10)          ----
__device__ __forceinline__ void flush16(int d, float4 a0, float4 a1, float4 a2, float4 a3) {
    float* mp = &g_m[(size_t)d * 16];
    asm volatile("red.global.add.v4.f32 [%0], {%1, %2, %3, %4};"
                 :: "l"(mp + 0),  "f"(a0.x), "f"(a0.y), "f"(a0.z), "f"(a0.w) : "memory");
    asm volatile("red.global.add.v4.f32 [%0], {%1, %2, %3, %4};"
                 :: "l"(mp + 4),  "f"(a1.x), "f"(a1.y), "f"(a1.z), "f"(a1.w) : "memory");
    asm volatile("red.global.add.v4.f32 [%0], {%1, %2, %3, %4};"
                 :: "l"(mp + 8),  "f"(a2.x), "f"(a2.y), "f"(a2.z), "f"(a2.w) : "memory");
    asm volatile("red.global.add.v4.f32 [%0], {%1, %2, %3, %4};"
                 :: "l"(mp + 12), "f"(a3.x), "f"(a3.y), "f"(a3.z), "f"(a3.w) : "memory");
}

__global__ void k_runsum16(int Etot) {
    int t = blockIdx.x * blockDim.x + threadIdx.x;
    int start = t * CHUNK;
    if (start >= Etot) return;
    int cnt = Etot - start; if (cnt > CHUNK) cnt = CHUNK;

    // preload edge ids (independent of everything downstream)
    int sbuf[CHUNK], dbuf[CHUNK];
    if (cnt == CHUNK) {
        #pragma unroll
        for (int j = 0; j < CHUNK / 2; j++) {
            int4 q = __ldg(&g_sortv[(size_t)t * (CHUNK / 2) + j]);
            sbuf[2*j] = q.x; dbuf[2*j] = q.y; sbuf[2*j+1] = q.z; dbuf[2*j+1] = q.w;
        }
    } else {
        for (int j = 0; j < cnt; j++) {
            int2 q = __ldg((const int2*)g_sortv + start + j);
            sbuf[j] = q.x; dbuf[j] = q.y;
        }
    }

    const float4* hp = (const float4*)&g_h1[(size_t)sbuf[0] * 16];
    float4 a0 = __ldg(hp + 0), a1 = __ldg(hp + 1), a2 = __ldg(hp + 2), a3 = __ldg(hp + 3);
    int cur = dbuf[0];
    #pragma unroll
    for (int j = 1; j < CHUNK; j++) {
        if (j >= cnt) break;
        const float4* vp = (const float4*)&g_h1[(size_t)sbuf[j] * 16];
        float4 v0 = __ldg(vp + 0), v1 = __ldg(vp + 1), v2 = __ldg(vp + 2), v3 = __ldg(vp + 3);
        if (dbuf[j] != cur) {
            flush16(cur, a0, a1, a2, a3);
            cur = dbuf[j];
            a0 = v0; a1 = v1; a2 = v2; a3 = v3;
        } else {
            a0.x += v0.x; a0.y += v0.y; a0.z += v0.z; a0.w += v0.w;
            a1.x += v1.x; a1.y += v1.y; a1.z += v1.z; a1.w += v1.w;
            a2.x += v2.x; a2.y += v2.y; a2.z += v2.z; a2.w += v2.w;
            a3.x += v3.x; a3.y += v3.y; a3.z += v3.z; a3.w += v3.w;
        }
    }
    flush16(cur, a0, a1, a2, a3);
}

// ---------------- combine + relu + layer-2 node transform (zero g_o2) -------
__global__ void k_combine(const float* __restrict__ b1, const float* __restrict__ W2) {
    __shared__ float sW2[48], sb1[48];
    if (threadIdx.x < 48) {
        sW2[threadIdx.x] = W2[threadIdx.x];
        sb1[threadIdx.x] = b1[threadIdx.x];
    }
    __syncthreads();
    int n = blockIdx.x * blockDim.x + threadIdx.x;
    if (n >= NN) return;
    float acc[16];
    #pragma unroll
    for (int f = 0; f < 16; f++) acc[f] = 0.f;
    #pragma unroll
    for (int r = 0; r < 3; r++) {
        float ain = rs_of(g_din[r * NN + n]);
        const float* mp = &g_m[(size_t)(r * NN + n) * 16];
        #pragma unroll
        for (int f = 0; f < 16; f += 4) {
            float4 v = *(const float4*)(mp + f);
            acc[f]   += v.x * ain + sb1[r*16 + f];
            acc[f+1] += v.y * ain + sb1[r*16 + f + 1];
            acc[f+2] += v.z * ain + sb1[r*16 + f + 2];
            acc[f+3] += v.w * ain + sb1[r*16 + f + 3];
        }
    }
    #pragma unroll
    for (int f = 0; f < 16; f++) acc[f] = fmaxf(acc[f], 0.f);
    #pragma unroll
    for (int r = 0; r < 3; r++) {
        float aout = rs_of(g_dout[r * NN + n]);
        float dot = 0.f;
        #pragma unroll
        for (int f = 0; f < 16; f++) dot += acc[f] * sW2[r*16 + f];
        g_s [r * NN + n] = aout * dot;
        g_o2[r * NN + n] = 0.f;
    }
}

// ---- layer 2 aggregate: same run-merged walk, scalar values ----------------
__global__ void k_runsum1(int Etot) {
    int t = blockIdx.x * blockDim.x + threadIdx.x;
    int start = t * CHUNK;
    if (start >= Etot) return;
    int cnt = Etot - start; if (cnt > CHUNK) cnt = CHUNK;

    int sbuf[CHUNK], dbuf[CHUNK];
    if (cnt == CHUNK) {
        #pragma unroll
        for (int j = 0; j < CHUNK / 2; j++) {
            int4 q = __ldg(&g_sortv[(size_t)t * (CHUNK / 2) + j]);
            sbuf[2*j] = q.x; dbuf[2*j] = q.y; sbuf[2*j+1] = q.z; dbuf[2*j+1] = q.w;
        }
    } else {
        for (int j = 0; j < cnt; j++) {
            int2 q = __ldg((const int2*)g_sortv + start + j);
            sbuf[j] = q.x; dbuf[j] = q.y;
        }
    }

    float acc = __ldg(&g_s[sbuf[0]]);
    int cur = dbuf[0];
    #pragma unroll
    for (int j = 1; j < CHUNK; j++) {
        if (j >= cnt) break;
        float v = __ldg(&g_s[sbuf[j]]);
        if (dbuf[j] != cur) {
            atomicAdd(&g_o2[cur], acc);
            cur = dbuf[j];
            acc = v;
        } else {
            acc += v;
        }
    }
    atomicAdd(&g_o2[cur], acc);
}

// ---------------- final ----------------
__global__ void k_final(float* __restrict__ out, const float* __restrict__ b2) {
    int n = blockIdx.x * blockDim.x + threadIdx.x;
    if (n >= NN) return;
    float o = __ldg(b2) + __ldg(b2 + 1) + __ldg(b2 + 2);
    #pragma unroll
    for (int r = 0; r < 3; r++)
        o += g_o2[r * NN + n] * rs_of(g_din[r * NN + n]);
    out[n] = o;
}

// ---------------- host ----------------
extern "C" void kernel_launch(void* const* d_in, const int* in_sizes, int n_in,
                              void* d_out, int out_size) {
    const float* x  = (const float*)d_in[0];
    const void*  src[3] = { d_in[1], d_in[3], d_in[5] };
    const void*  dst[3] = { d_in[2], d_in[4], d_in[6] };
    int          E[3]   = { in_sizes[1], in_sizes[3], in_sizes[5] };
    const float* W1 = (const float*)d_in[7];
    const float* b1 = (const float*)d_in[8];
    const float* W2 = (const float*)d_in[9];
    const float* b2 = (const float*)d_in[10];
    float*       out = (float*)d_out;

    int Etot = E[0] + E[1] + E[2];
    if (Etot > EMAX) Etot = EMAX;

    int nprobe = E[0] < 2048 ? E[0] : 2048;
    k_detect<<<1, NT>>>((const unsigned*)d_in[1], nprobe);

    k_zero<<<(NSEG + NT - 1) / NT, NT>>>();
    int eoff = 0;
    for (int r = 0; r < 3; r++) {
        k_degc<<<(E[r] + NT - 1) / NT, NT>>>(src[r], dst[r], E[r], r, eoff);
        eoff += E[r];
    }

    int nblk = (NSEG + SCAN_BS - 1) / SCAN_BS;   // 147
    k_scan1<<<nblk, SCAN_BS>>>();
    k_scan2<<<1, 256>>>(nblk);
    k_scan3<<<nblk, SCAN_BS>>>();
    k_fill<<<(Etot + NT - 1) / NT, NT>>>(Etot);

    k_layer1_node<<<(NN + NT - 1) / NT, NT>>>(x, W1);

    int nthr = (Etot + CHUNK - 1) / CHUNK;
    k_runsum16<<<(nthr + NT - 1) / NT, NT>>>(Etot);

    k_combine<<<(NN + NT - 1) / NT, NT>>>(b1, W2);
    k_runsum1<<<(nthr + NT - 1) / NT, NT>>>(Etot);

    k_final<<<(NN + NT - 1) / NT, NT>>>(out, b2);
}

// round 10
// speedup vs baseline: 1.6292x; 1.1786x over previous
#include <cuda_runtime.h>

#define NN   50000
#define NSEG 150000          // 3 relations x NN segments, v = r*NN + node
#define NT   256
#define EMAX 4500000

// ---------------- scratch (static device globals; no allocs) ----------------
__device__ int    g_is64;                // 1 if edge indices are int64
__device__ int    g_cnt[6 * NN];         // [2r]=deg_out(src), [2r+1]=deg_in(dst)
__device__ int2   g_edges[EMAX];         // compact (src seg, dst seg)
__device__ float  g_h1 [NSEG * 16];      // rsqrt(dout)-scaled layer-1 features
__device__ float4 g_m4 [4 * NSEG];       // CHUNK-PLANAR accumulators: [c*NSEG + seg]
__device__ float  g_s  [NSEG];           // scalar layer-2 messages
__device__ float  g_o2 [NSEG];           // scalar layer-2 accumulators

// ---------------- dtype detection ----------------
__global__ void k_detect(const unsigned* __restrict__ p, int n) {
    __shared__ int found;
    if (threadIdx.x == 0) found = 0;
    __syncthreads();
    int f = 0;
    for (int i = threadIdx.x; i < n; i += blockDim.x)
        if (p[2 * i + 1] != 0u) f = 1;
    if (f) atomicOr(&found, 1);
    __syncthreads();
    if (threadIdx.x == 0) g_is64 = found ? 0 : 1;
}

__device__ __forceinline__ int ldidx(const void* __restrict__ p, int i) {
    return g_is64 ? (int)__ldg((const long long*)p + i)
                  : __ldg((const int*)p + i);
}

__device__ __forceinline__ float rs_of(int cnt) {
    return rsqrtf((float)(cnt > 0 ? cnt : 1));
}

// ---------------- zero counters ----------------
__global__ void k_zero_cnt() {
    int i = blockIdx.x * blockDim.x + threadIdx.x;
    if (i < 6 * NN) g_cnt[i] = 0;
}

// ---------------- degrees + index compaction (single pass) ----------------
__global__ void k_degc(const void* __restrict__ src, const void* __restrict__ dst,
                       int E, int r, int eoff) {
    int e = blockIdx.x * blockDim.x + threadIdx.x;
    if (e >= E) return;
    int s = ldidx(src, e);
    int d = ldidx(dst, e);
    atomicAdd(&g_cnt[(2 * r)     * NN + s], 1);
    atomicAdd(&g_cnt[(2 * r + 1) * NN + d], 1);
    g_edges[eoff + e] = make_int2(r * NN + s, r * NN + d);
}

// ---------------- layer 1: per-node transform (and zero g_m4) ---------------
__global__ void k_layer1_node(const float* __restrict__ x, const float* __restrict__ W1) {
    __shared__ float sW[3 * 32 * 16];
    for (int i = threadIdx.x; i < 1536; i += blockDim.x) sW[i] = W1[i];
    __syncthreads();
    int n = blockIdx.x * blockDim.x + threadIdx.x;
    if (n >= NN) return;
    float xv[32];
    #pragma unroll
    for (int j = 0; j < 8; j++) {
        float4 v = __ldg((const float4*)(x + (size_t)n * 32) + j);
        xv[4*j] = v.x; xv[4*j+1] = v.y; xv[4*j+2] = v.z; xv[4*j+3] = v.w;
    }
    #pragma unroll
    for (int r = 0; r < 3; r++) {
        float a = rs_of(g_cnt[(2 * r) * NN + n]);
        float y[16];
        #pragma unroll
        for (int f = 0; f < 16; f++) y[f] = 0.f;
        #pragma unroll
        for (int j = 0; j < 32; j++) {
            float xj = xv[j];
            #pragma unroll
            for (int f = 0; f < 16; f++)
                y[f] += xj * sW[r * 512 + j * 16 + f];
        }
        int seg = r * NN + n;
        float* hp = &g_h1[(size_t)seg * 16];
        #pragma unroll
        for (int c = 0; c < 4; c++) {
            *(float4*)(hp + c * 4) =
                make_float4(a*y[4*c], a*y[4*c+1], a*y[4*c+2], a*y[4*c+3]);
            g_m4[(size_t)c * NSEG + seg] = make_float4(0.f, 0.f, 0.f, 0.f);
        }
    }
}

// ---- layer 1 scatter: 4 threads/edge, RED.128 into 4 DIFFERENT L2 slices ---
__global__ void k_scatter16(int Etot) {
    long long t = (long long)blockIdx.x * blockDim.x + threadIdx.x;
    if (t >= (long long)Etot * 4) return;
    int e = (int)(t >> 2), c = (int)(t & 3);
    int2 ed = *(const int2*)&g_edges[e];          // 4 lanes same addr: L1 broadcast
    const float4 v = __ldg((const float4*)&g_h1[(size_t)ed.x * 16] + c);
    float* mp = (float*)&g_m4[(size_t)c * NSEG + ed.y];   // planar: slice-spread
    asm volatile("red.global.add.v4.f32 [%0], {%1, %2, %3, %4};"
                 :: "l"(mp), "f"(v.x), "f"(v.y), "f"(v.z), "f"(v.w) : "memory");
}

// ---------------- combine + relu + layer-2 node transform (zero g_o2) -------
__global__ void k_combine(const float* __restrict__ b1, const float* __restrict__ W2) {
    __shared__ float sW2[48], sb1[48];
    if (threadIdx.x < 48) {
        sW2[threadIdx.x] = W2[threadIdx.x];
        sb1[threadIdx.x] = b1[threadIdx.x];
    }
    __syncthreads();
    int n = blockIdx.x * blockDim.x + threadIdx.x;
    if (n >= NN) return;
    float acc[16];
    #pragma unroll
    for (int f = 0; f < 16; f++) acc[f] = 0.f;
    #pragma unroll
    for (int r = 0; r < 3; r++) {
        int seg = r * NN + n;
        float ain = rs_of(g_cnt[(2 * r + 1) * NN + n]);
        #pragma unroll
        for (int c = 0; c < 4; c++) {
            float4 v = g_m4[(size_t)c * NSEG + seg];
            acc[4*c]   += v.x * ain + sb1[r*16 + 4*c];
            acc[4*c+1] += v.y * ain + sb1[r*16 + 4*c + 1];
            acc[4*c+2] += v.z * ain + sb1[r*16 + 4*c + 2];
            acc[4*c+3] += v.w * ain + sb1[r*16 + 4*c + 3];
        }
    }
    #pragma unroll
    for (int f = 0; f < 16; f++) acc[f] = fmaxf(acc[f], 0.f);
    #pragma unroll
    for (int r = 0; r < 3; r++) {
        float aout = rs_of(g_cnt[(2 * r) * NN + n]);
        float dot = 0.f;
        #pragma unroll
        for (int f = 0; f < 16; f++) dot += acc[f] * sW2[r*16 + f];
        g_s [r * NN + n] = aout * dot;
        g_o2[r * NN + n] = 0.f;
    }
}

// ---------------- layer 2: scalar edge scatter ----------------
__global__ void k_scatter1(int Etot) {
    int e = blockIdx.x * blockDim.x + threadIdx.x;
    if (e >= Etot) return;
    int2 ed = __ldg((const int2*)&g_edges[e]);
    float v = __ldg(&g_s[ed.x]);
    atomicAdd(&g_o2[ed.y], v);
}

// ---------------- final ----------------
__global__ void k_final(float* __restrict__ out, const float* __restrict__ b2) {
    int n = blockIdx.x * blockDim.x + threadIdx.x;
    if (n >= NN) return;
    float o = __ldg(b2) + __ldg(b2 + 1) + __ldg(b2 + 2);
    #pragma unroll
    for (int r = 0; r < 3; r++)
        o += g_o2[r * NN + n] * rs_of(g_cnt[(2 * r + 1) * NN + n]);
    out[n] = o;
}

// ---------------- host ----------------
extern "C" void kernel_launch(void* const* d_in, const int* in_sizes, int n_in,
                              void* d_out, int out_size) {
    const float* x  = (const float*)d_in[0];
    const void*  src[3] = { d_in[1], d_in[3], d_in[5] };
    const void*  dst[3] = { d_in[2], d_in[4], d_in[6] };
    int          E[3]   = { in_sizes[1], in_sizes[3], in_sizes[5] };
    const float* W1 = (const float*)d_in[7];
    const float* b1 = (const float*)d_in[8];
    const float* W2 = (const float*)d_in[9];
    const float* b2 = (const float*)d_in[10];
    float*       out = (float*)d_out;

    int Etot = E[0] + E[1] + E[2];
    if (Etot > EMAX) Etot = EMAX;

    int nprobe = E[0] < 2048 ? E[0] : 2048;
    k_detect<<<1, NT>>>((const unsigned*)d_in[1], nprobe);

    k_zero_cnt<<<(6 * NN + NT - 1) / NT, NT>>>();
    int eoff = 0;
    for (int r = 0; r < 3; r++) {
        k_degc<<<(E[r] + NT - 1) / NT, NT>>>(src[r], dst[r], E[r], r, eoff);
        eoff += E[r];
    }

    k_layer1_node<<<(NN + NT - 1) / NT, NT>>>(x, W1);
    {
        long long work = (long long)Etot * 4;
        int blocks = (int)((work + NT - 1) / NT);
        k_scatter16<<<blocks, NT>>>(Etot);
    }

    k_combine<<<(NN + NT - 1) / NT, NT>>>(b1, W2);
    k_scatter1<<<(Etot + NT - 1) / NT, NT>>>(Etot);

    k_final<<<(NN + NT - 1) / NT, NT>>>(out, b2);
}